// round 9
// baseline (speedup 1.0000x reference)
#include <cuda_runtime.h>

// ---------------------------------------------------------------------------
// EventGRUBayes — two-kernel split.
// K1 (sequential): warp-independent recurrence, 128 blocks x 64 threads,
//     4 samples/warp, gates+ODE+events only; h_rec streamed to g_hrec.
// K2 (parallel): batched output head over all 501*1024 (t,b) pairs.
// ---------------------------------------------------------------------------

#define B_     1024
#define NEV    400
#define NSTEPS 500
#define TOT_   (NEV * 256)
#define DT_    0.01f

typedef unsigned long long ull;
typedef ulonglong2 ul2;

// K1 smem float offsets (rows padded 64->68 / 8->12)
#define OF_GHR 0
#define OF_GHZ 4352
#define OF_GHH 8704
#define OF_WHH 13056
#define OF_WIH 26112
#define OF_BIH 28416
#define OF_BHH 28608
#define OF_GXB 28800
#define OF_HS  28992
#define OF_RS  29504
#define OF_WIN 30016
#define OF_XV  30032
#define SM_MAIN 30160        // 120640 bytes

// K2 smem float offsets
#define SH_W1  0             // 128*68
#define SH_H   8704          // 8 warps * 512
#define SH_OB1 12800
#define SH_W2  12928
#define SH_OB2 13184
#define SM_HEAD 13188        // 52752 bytes

__device__ int   g_winner[NEV * B_];
__device__ float g_hrec[(size_t)(NSTEPS + 1) * B_ * 64];   // [t][b][64]

__global__ void winner_init_k() {
    int i = blockIdx.x * blockDim.x + threadIdx.x;
    if (i < NEV * B_) g_winner[i] = -1;
}
__global__ void winner_scatter_k(const int* __restrict__ sid) {
    int j = blockIdx.x * blockDim.x + threadIdx.x;
    if (j < TOT_) atomicMax(&g_winner[(j >> 8) * B_ + sid[j]], j);
}

__device__ __forceinline__ float sigm(float x) {
    return __fdividef(1.f, 1.f + __expf(-x));
}
__device__ __forceinline__ float tanh_f(float x) {
    float xc = fminf(fmaxf(x, -15.f), 15.f);
    float e  = __expf(-2.f * xc);
    return __fdividef(1.f - e, 1.f + e);
}
#define FMA2(d, a, b, c) \
    asm("fma.rn.f32x2 %0, %1, %2, %3;" : "=l"(d) : "l"(a), "l"(b), "l"(c))
__device__ __forceinline__ float hadd2(ull v) {
    unsigned lo, hi;
    asm("mov.b64 {%0, %1}, %2;" : "=r"(lo), "=r"(hi) : "l"(v));
    return __uint_as_float(lo) + __uint_as_float(hi);
}
__device__ __forceinline__ float dot8(const float* __restrict__ w, float4 xa, float4 xb) {
    float4 A  = *reinterpret_cast<const float4*>(w);
    float4 Bv = *reinterpret_cast<const float4*>(w + 4);
    float s = A.x * xa.x;
    s = fmaf(A.y,  xa.y, s); s = fmaf(A.z,  xa.z, s); s = fmaf(A.w,  xa.w, s);
    s = fmaf(Bv.x, xb.x, s); s = fmaf(Bv.y, xb.y, s);
    s = fmaf(Bv.z, xb.z, s); s = fmaf(Bv.w, xb.w, s);
    return s;
}

// GRU-Bayes event update for one sample (warp-collective, h in smem)
__device__ __forceinline__ void event_upd(
    float* __restrict__ hs, const float* __restrict__ xv,
    const float* __restrict__ sm,
    float ebr1, float ebr2, float ebz1, float ebz2,
    float ebi1, float ebi2, float ebh1, float ebh2,
    int lane, int o2)
{
    float4 xa = *(const float4*)xv, xb = *(const float4*)(xv + 4);
    float gir1 = dot8(sm + OF_WIH + lane*12,       xa, xb);
    float gir2 = dot8(sm + OF_WIH + (32+lane)*12,  xa, xb);
    float giz1 = dot8(sm + OF_WIH + (64+lane)*12,  xa, xb);
    float giz2 = dot8(sm + OF_WIH + (96+lane)*12,  xa, xb);
    float gin1 = dot8(sm + OF_WIH + (128+lane)*12, xa, xb);
    float gin2 = dot8(sm + OF_WIH + (160+lane)*12, xa, xb);
    const ul2* pE1 = (const ul2*)(sm + OF_WHH + lane*68);
    ull a1=0,a2=0,a3=0,a4=0,a5=0,a6=0;
    const ul2* hp = (const ul2*)hs;
    #pragma unroll
    for (int i = 0; i < 16; i++) {
        ul2 hv = hp[i];
        ul2 w1 = pE1[i],        w2 = pE1[i + 544];
        ul2 w3 = pE1[i + 1088], w4 = pE1[i + 1632];
        ul2 w5 = pE1[i + 2176], w6 = pE1[i + 2720];
        FMA2(a1, w1.x, hv.x, a1); FMA2(a1, w1.y, hv.y, a1);
        FMA2(a2, w2.x, hv.x, a2); FMA2(a2, w2.y, hv.y, a2);
        FMA2(a3, w3.x, hv.x, a3); FMA2(a3, w3.y, hv.y, a3);
        FMA2(a4, w4.x, hv.x, a4); FMA2(a4, w4.y, hv.y, a4);
        FMA2(a5, w5.x, hv.x, a5); FMA2(a5, w5.y, hv.y, a5);
        FMA2(a6, w6.x, hv.x, a6); FMA2(a6, w6.y, hv.y, a6);
    }
    float h1o = hs[lane], h2o = hs[o2];
    float r1 = sigm(gir1 + hadd2(a1) + ebr1);
    float r2 = sigm(gir2 + hadd2(a2) + ebr2);
    float z1 = sigm(giz1 + hadd2(a3) + ebz1);
    float z2 = sigm(giz2 + hadd2(a4) + ebz2);
    float n1 = tanh_f(gin1 + ebi1 + r1 * (hadd2(a5) + ebh1));
    float n2 = tanh_f(gin2 + ebi2 + r2 * (hadd2(a6) + ebh2));
    float h1n = fmaf(z1, h1o - n1, n1);      // (1-z)n + z h
    float h2n = fmaf(z2, h2o - n2, n2);
    __syncwarp();
    hs[lane] = h1n; hs[o2] = h2n;
    __syncwarp();
}

__global__ __launch_bounds__(64, 1)
void ev_gru_main(
    const float* __restrict__ X,
    const float* __restrict__ covs,
    const float* __restrict__ cW1, const float* __restrict__ cb1,
    const float* __restrict__ cW2, const float* __restrict__ cb2,
    const float* __restrict__ gWih, const float* __restrict__ gWhh,
    const float* __restrict__ gbih, const float* __restrict__ gbhh,
    const float* __restrict__ gxb,
    const float* __restrict__ ghrW, const float* __restrict__ ghzW,
    const float* __restrict__ ghhW)
{
    extern __shared__ float sm[];
    const int tid = threadIdx.x, blk = blockIdx.x;
    const int warp = tid >> 5, lane = tid & 31, o2 = lane + 32;
    int* swin = (int*)(sm + OF_WIN);

    // ---- staging (stride 64) ----
    for (int i = tid; i < 64*64; i += 64) {
        int r = i >> 6, c = i & 63;
        sm[OF_GHR + r*68 + c] = ghrW[i];
        sm[OF_GHZ + r*68 + c] = ghzW[i];
        sm[OF_GHH + r*68 + c] = ghhW[i];
    }
    for (int i = tid; i < 192*64; i += 64) {
        int r = i >> 6, c = i & 63;
        sm[OF_WHH + r*68 + c] = gWhh[i];
    }
    for (int i = tid; i < 192*8; i += 64) {
        int r = i >> 3, c = i & 7;
        sm[OF_WIH + r*12 + c] = gWih[i];
    }
    for (int i = tid; i < 192; i += 64) {
        sm[OF_BIH + i] = gbih[i];
        sm[OF_BHH + i] = gbhh[i];
        sm[OF_GXB + i] = gxb[i];
    }

    // ---- h0 init: warp w -> samples w*4..w*4+3 ----
    #pragma unroll
    for (int pick = 0; pick < 4; pick++) {
        const int s = warp*4 + pick, b = blk*8 + s;
        float* hs = sm + OF_HS + s*64;
        float* rs = sm + OF_RS + s*64;
        float t1 = __ldg(cb1 + lane), t2 = __ldg(cb1 + o2);
        #pragma unroll
        for (int k = 0; k < 16; k++) {
            float cv = __ldg(covs + b*16 + k);
            t1 = fmaf(cv, __ldg(cW1 + lane*16 + k), t1);
            t2 = fmaf(cv, __ldg(cW1 + o2*16   + k), t2);
        }
        rs[lane] = fmaxf(t1, 0.f); rs[o2] = fmaxf(t2, 0.f);
        __syncwarp();
        float a1 = __ldg(cb2 + lane), a2 = __ldg(cb2 + o2);
        #pragma unroll 8
        for (int c = 0; c < 64; c++) {
            float tv = rs[c];
            a1 = fmaf(tv, __ldg(cW2 + lane*64 + c), a1);
            a2 = fmaf(tv, __ldg(cW2 + o2*64   + c), a2);
        }
        __syncwarp();
        hs[lane] = tanh_f(a1); hs[o2] = tanh_f(a2);
        __syncwarp();
    }
    if (lane < 4) {
        const int s4 = warp*4 + lane;
        int w = __ldg(g_winner + blk*8 + s4);
        swin[s4] = w;
        if (w >= 0) {
            const float4* xp = (const float4*)(X + (size_t)w*8);
            float4 xa = __ldg(xp), xb = __ldg(xp + 1);
            float4* dst = (float4*)(sm + OF_XV + s4*8);
            dst[0] = xa; dst[1] = xb;
        }
    }
    __syncthreads();

    // ---- stationary pointers / scalars ----
    const ul2* pR1 = (const ul2*)(sm + OF_GHR + lane*68);
    const ul2* pR2 = (const ul2*)(sm + OF_GHR + (lane+32)*68);
    const ul2* pZ1 = (const ul2*)(sm + OF_GHZ + lane*68);
    const ul2* pZ2 = (const ul2*)(sm + OF_GHZ + (lane+32)*68);
    const ul2* pU1 = (const ul2*)(sm + OF_GHH + lane*68);
    const ul2* pU2 = (const ul2*)(sm + OF_GHH + (lane+32)*68);
    const ul2* hpW = (const ul2*)(sm + OF_HS + warp*256);   // [s*16+i]
    const ul2* rpW = (const ul2*)(sm + OF_RS + warp*256);

    const float xr1 = sm[OF_GXB + lane],       xr2 = sm[OF_GXB + o2];
    const float xz1 = sm[OF_GXB + 64 + lane],  xz2 = sm[OF_GXB + 64 + o2];
    const float xh1 = sm[OF_GXB + 128 + lane], xh2 = sm[OF_GXB + 128 + o2];
    const float ebr1 = sm[OF_BIH + lane]      + sm[OF_BHH + lane];
    const float ebr2 = sm[OF_BIH + o2]        + sm[OF_BHH + o2];
    const float ebz1 = sm[OF_BIH + 64 + lane] + sm[OF_BHH + 64 + lane];
    const float ebz2 = sm[OF_BIH + 64 + o2]   + sm[OF_BHH + 64 + o2];
    const float ebi1 = sm[OF_BIH + 128 + lane], ebi2 = sm[OF_BIH + 128 + o2];
    const float ebh1 = sm[OF_BHH + 128 + lane], ebh2 = sm[OF_BHH + 128 + o2];

    float zlo[4], zhi[4];

    // ================= main loop (warp-independent) =================
    for (int t = 0; ; t++) {
        const int pb = t & 1;
        int pw = -1;
        const bool pf = (t + 1 < NEV) && (lane < 4);
        if (pf) pw = __ldg(g_winner + (t+1)*B_ + blk*8 + warp*4 + lane);

        // ---- events ----
        if (t < NEV) {
            #pragma unroll
            for (int s = 0; s < 4; s++) {
                int w = swin[pb*8 + warp*4 + s];
                if (w >= 0)
                    event_upd(sm + OF_HS + (warp*4+s)*64,
                              sm + OF_XV + pb*64 + (warp*4+s)*8, sm,
                              ebr1,ebr2,ebz1,ebz2,ebi1,ebi2,ebh1,ebh2,
                              lane, o2);
            }
        }
        __syncwarp();

        // ---- h_rec store (post-event, pre-ODE) ----
        {
            float* base = g_hrec + ((size_t)t*B_ + blk*8 + warp*4)*64;
            #pragma unroll
            for (int s = 0; s < 4; s++) {
                float2 v = *(const float2*)(sm + OF_HS + (warp*4+s)*64 + lane*2);
                *(float2*)(base + s*64 + lane*2) = v;
            }
        }
        if (t == NSTEPS) break;

        // ---- PASS1: gates r,z — 4 rowsets x 4 samples ----
        ull aR1[4], aR2[4], aZ1[4], aZ2[4];
        #pragma unroll
        for (int s = 0; s < 4; s++) { aR1[s]=0; aR2[s]=0; aZ1[s]=0; aZ2[s]=0; }
        #pragma unroll
        for (int i = 0; i < 16; i++) {
            ul2 w1 = pR1[i], w2 = pR2[i], w3 = pZ1[i], w4 = pZ2[i];
            #pragma unroll
            for (int s = 0; s < 4; s++) {
                ul2 hv = hpW[s*16 + i];
                FMA2(aR1[s], w1.x, hv.x, aR1[s]); FMA2(aR1[s], w1.y, hv.y, aR1[s]);
                FMA2(aR2[s], w2.x, hv.x, aR2[s]); FMA2(aR2[s], w2.y, hv.y, aR2[s]);
                FMA2(aZ1[s], w3.x, hv.x, aZ1[s]); FMA2(aZ1[s], w3.y, hv.y, aZ1[s]);
                FMA2(aZ2[s], w4.x, hv.x, aZ2[s]); FMA2(aZ2[s], w4.y, hv.y, aZ2[s]);
            }
        }
        #pragma unroll
        for (int s = 0; s < 4; s++) {
            float hlo = sm[OF_HS + (warp*4+s)*64 + lane];
            float hhi = sm[OF_HS + (warp*4+s)*64 + o2];
            float rlo = sigm(hadd2(aR1[s]) + xr1);
            float rhi = sigm(hadd2(aR2[s]) + xr2);
            zlo[s] = sigm(hadd2(aZ1[s]) + xz1);
            zhi[s] = sigm(hadd2(aZ2[s]) + xz2);
            sm[OF_RS + (warp*4+s)*64 + lane] = rlo * hlo;
            sm[OF_RS + (warp*4+s)*64 + o2]   = rhi * hhi;
        }
        if (pf) {
            swin[(pb ^ 1)*8 + warp*4 + lane] = pw;
            if (pw >= 0) {
                const float4* xp = (const float4*)(X + (size_t)pw*8);
                float4 xa = __ldg(xp), xb = __ldg(xp + 1);
                float4* dst = (float4*)(sm + OF_XV + (pb^1)*64 + (warp*4+lane)*8);
                dst[0] = xa; dst[1] = xb;
            }
        }
        __syncwarp();

        // ---- PASS2: ghh on (r*h) — 2 rowsets x 4 samples; Euler ----
        ull u1[4], u2[4];
        #pragma unroll
        for (int s = 0; s < 4; s++) { u1[s]=0; u2[s]=0; }
        #pragma unroll
        for (int i = 0; i < 16; i++) {
            ul2 wg1 = pU1[i], wg2 = pU2[i];
            #pragma unroll
            for (int s = 0; s < 4; s++) {
                ul2 rv = rpW[s*16 + i];
                FMA2(u1[s], wg1.x, rv.x, u1[s]); FMA2(u1[s], wg1.y, rv.y, u1[s]);
                FMA2(u2[s], wg2.x, rv.x, u2[s]); FMA2(u2[s], wg2.y, rv.y, u2[s]);
            }
        }
        #pragma unroll
        for (int s = 0; s < 4; s++) {
            float hlo = sm[OF_HS + (warp*4+s)*64 + lane];
            float hhi = sm[OF_HS + (warp*4+s)*64 + o2];
            float ulo = tanh_f(xh1 + hadd2(u1[s]));
            float uhi = tanh_f(xh2 + hadd2(u2[s]));
            sm[OF_HS + (warp*4+s)*64 + lane] = fmaf(DT_*(1.f - zlo[s]), ulo - hlo, hlo);
            sm[OF_HS + (warp*4+s)*64 + o2]   = fmaf(DT_*(1.f - zhi[s]), uhi - hhi, hhi);
        }
        __syncwarp();
    }
}

// ---------------- K2: batched output head ----------------
__global__ __launch_bounds__(256)
void head_k(const float* __restrict__ oW1, const float* __restrict__ ob1,
            const float* __restrict__ oW2, const float* __restrict__ ob2,
            float* __restrict__ out)
{
    extern __shared__ float sm[];
    const int tid = threadIdx.x, warp = tid >> 5, lane = tid & 31;

    for (int i = tid; i < 128*64; i += 256) {
        int r = i >> 6, c = i & 63;
        sm[SH_W1 + r*68 + c] = oW1[i];
    }
    if (tid < 128) sm[SH_OB1 + tid] = ob1[tid];
    sm[SH_W2 + tid] = oW2[tid];
    if (tid < 2) sm[SH_OB2 + tid] = ob2[tid];

    // load 8 contiguous (t,b) pairs' h (512 floats) into this warp's slot
    const size_t base = ((size_t)blockIdx.x*8 + warp)*8;   // first pair index
    {
        const float4* hb = (const float4*)(g_hrec + base*64);
        float4* sh4 = (float4*)(sm + SH_H + warp*512);
        #pragma unroll
        for (int k = 0; k < 4; k++) sh4[k*32 + lane] = __ldg(hb + k*32 + lane);
    }
    __syncthreads();

    const ul2* pA = (const ul2*)(sm + SH_W1 + lane*68);
    const ul2* pB = (const ul2*)(sm + SH_W1 + (lane+32)*68);
    const ul2* pC = (const ul2*)(sm + SH_W1 + (lane+64)*68);
    const ul2* pD = (const ul2*)(sm + SH_W1 + (lane+96)*68);
    const ul2* hw = (const ul2*)(sm + SH_H + warp*512);
    const float hb0 = sm[SH_OB1 + lane],      hb1 = sm[SH_OB1 + lane + 32];
    const float hb2 = sm[SH_OB1 + lane + 64], hb3 = sm[SH_OB1 + lane + 96];
    const float w200 = sm[SH_W2 + lane],      w201 = sm[SH_W2 + lane + 32];
    const float w202 = sm[SH_W2 + lane + 64], w203 = sm[SH_W2 + lane + 96];
    const float w210 = sm[SH_W2 + 128 + lane],      w211 = sm[SH_W2 + 128 + lane + 32];
    const float w212 = sm[SH_W2 + 128 + lane + 64], w213 = sm[SH_W2 + 128 + lane + 96];
    const float b20 = sm[SH_OB2], b21 = sm[SH_OB2 + 1];

    ull aA[8], aB[8], aC[8], aD[8];
    #pragma unroll
    for (int p = 0; p < 8; p++) { aA[p]=0; aB[p]=0; aC[p]=0; aD[p]=0; }
    #pragma unroll
    for (int i = 0; i < 16; i++) {
        ul2 wa = pA[i], wb = pB[i], wc = pC[i], wd = pD[i];
        #pragma unroll
        for (int p = 0; p < 8; p++) {
            ul2 hv = hw[p*16 + i];
            FMA2(aA[p], wa.x, hv.x, aA[p]); FMA2(aA[p], wa.y, hv.y, aA[p]);
            FMA2(aB[p], wb.x, hv.x, aB[p]); FMA2(aB[p], wb.y, hv.y, aB[p]);
            FMA2(aC[p], wc.x, hv.x, aC[p]); FMA2(aC[p], wc.y, hv.y, aC[p]);
            FMA2(aD[p], wd.x, hv.x, aD[p]); FMA2(aD[p], wd.y, hv.y, aD[p]);
        }
    }
    #pragma unroll
    for (int p = 0; p < 8; p++) {
        float d0 = fmaxf(hadd2(aA[p]) + hb0, 0.f);
        float d1 = fmaxf(hadd2(aB[p]) + hb1, 0.f);
        float d2 = fmaxf(hadd2(aC[p]) + hb2, 0.f);
        float d3 = fmaxf(hadd2(aD[p]) + hb3, 0.f);
        float p0 = d0*w200; p0 = fmaf(d1,w201,p0); p0 = fmaf(d2,w202,p0); p0 = fmaf(d3,w203,p0);
        float p1 = d0*w210; p1 = fmaf(d1,w211,p1); p1 = fmaf(d2,w212,p1); p1 = fmaf(d3,w213,p1);
        #pragma unroll
        for (int s = 16; s > 0; s >>= 1) {
            p0 += __shfl_xor_sync(0xffffffffu, p0, s);
            p1 += __shfl_xor_sync(0xffffffffu, p1, s);
        }
        if (lane == 0) {
            float2 v = {p0 + b20, p1 + b21};
            *(float2*)(out + (base + p)*2) = v;
        }
    }
}

extern "C" void kernel_launch(void* const* d_in, const int* in_sizes, int n_in,
                              void* d_out, int out_size)
{
    (void)in_sizes; (void)n_in; (void)out_size;
    const float* X    = (const float*)d_in[2];
    const int*   sid  = (const int*)  d_in[3];
    const float* covs = (const float*)d_in[4];
    const float* cW1  = (const float*)d_in[6];
    const float* cb1  = (const float*)d_in[7];
    const float* cW2  = (const float*)d_in[8];
    const float* cb2  = (const float*)d_in[9];
    const float* gWih = (const float*)d_in[10];
    const float* gWhh = (const float*)d_in[11];
    const float* gbih = (const float*)d_in[12];
    const float* gbhh = (const float*)d_in[13];
    const float* gxb  = (const float*)d_in[15];
    const float* ghrW = (const float*)d_in[16];
    const float* ghzW = (const float*)d_in[17];
    const float* ghhW = (const float*)d_in[18];
    const float* oW1  = (const float*)d_in[19];
    const float* ob1  = (const float*)d_in[20];
    const float* oW2  = (const float*)d_in[21];
    const float* ob2  = (const float*)d_in[22];
    float* out = (float*)d_out;

    winner_init_k<<<(NEV*B_ + 255)/256, 256>>>();
    winner_scatter_k<<<(TOT_ + 255)/256, 256>>>(sid);

    size_t sm_main = SM_MAIN * sizeof(float);
    cudaFuncSetAttribute(ev_gru_main, cudaFuncAttributeMaxDynamicSharedMemorySize, (int)sm_main);
    ev_gru_main<<<B_/8, 64, sm_main>>>(X, covs, cW1, cb1, cW2, cb2,
                                       gWih, gWhh, gbih, gbhh, gxb,
                                       ghrW, ghzW, ghhW);

    size_t sm_head = SM_HEAD * sizeof(float);
    cudaFuncSetAttribute(head_k, cudaFuncAttributeMaxDynamicSharedMemorySize, (int)sm_head);
    head_k<<<(NSTEPS + 1) * B_ / 64, 256, sm_head>>>(oW1, ob1, oW2, ob2, out);
}

// round 10
// speedup vs baseline: 1.4153x; 1.4153x over previous
#include <cuda_runtime.h>

// ---------------------------------------------------------------------------
// EventGRUBayes — two-kernel split, both halves repaired.
// K1: R4's warp-independent recurrence (128 blk x 128 thr, 4 warps x 2
//     samples) WITHOUT the output head; h_rec streamed to g_hrec.
//     Warp-local winner/X prefetch (no cross-warp race).
// K2: batched head, 4 (t,b) pairs per warp, <=128 regs -> 2+ blocks/SM.
// ---------------------------------------------------------------------------

#define B_     1024
#define NEV    400
#define NSTEPS 500
#define TOT_   (NEV * 256)
#define DT_    0.01f

typedef unsigned long long ull;
typedef ulonglong2 ul2;

// K1 smem float offsets (rows padded 64->68 / 8->12)
#define OF_GHR 0
#define OF_GHZ 4352
#define OF_GHH 8704
#define OF_WHH 13056
#define OF_WIH 26112
#define OF_BIH 28416
#define OF_BHH 28608
#define OF_GXB 28800
#define OF_HS  28992
#define OF_RS  29504
#define OF_WIN 30016          // [2][8] ints
#define OF_XV  30032          // [2][8][8]
#define SM_MAIN 30160         // 120640 bytes

// K2 smem float offsets
#define SH_W1  0              // 128*68
#define SH_H   8704           // 8 warps * 256
#define SH_OB1 10752
#define SH_W2  10880
#define SH_OB2 11136
#define SM_HEAD 11140         // 44560 bytes

__device__ int   g_winner[NEV * B_];
__device__ float g_hrec[(size_t)(NSTEPS + 1) * B_ * 64];   // [t][b][64]

__global__ void winner_init_k() {
    int i = blockIdx.x * blockDim.x + threadIdx.x;
    if (i < NEV * B_) g_winner[i] = -1;
}
__global__ void winner_scatter_k(const int* __restrict__ sid) {
    int j = blockIdx.x * blockDim.x + threadIdx.x;
    if (j < TOT_) atomicMax(&g_winner[(j >> 8) * B_ + sid[j]], j);
}

__device__ __forceinline__ float sigm(float x) {
    return __fdividef(1.f, 1.f + __expf(-x));
}
__device__ __forceinline__ float tanh_f(float x) {
    float xc = fminf(fmaxf(x, -15.f), 15.f);
    float e  = __expf(-2.f * xc);
    return __fdividef(1.f - e, 1.f + e);
}
#define FMA2(d, a, b, c) \
    asm("fma.rn.f32x2 %0, %1, %2, %3;" : "=l"(d) : "l"(a), "l"(b), "l"(c))
__device__ __forceinline__ float hadd2(ull v) {
    unsigned lo, hi;
    asm("mov.b64 {%0, %1}, %2;" : "=r"(lo), "=r"(hi) : "l"(v));
    return __uint_as_float(lo) + __uint_as_float(hi);
}
__device__ __forceinline__ float dot8(const float* __restrict__ w, float4 xa, float4 xb) {
    float4 A  = *reinterpret_cast<const float4*>(w);
    float4 Bv = *reinterpret_cast<const float4*>(w + 4);
    float s = A.x * xa.x;
    s = fmaf(A.y,  xa.y, s); s = fmaf(A.z,  xa.z, s); s = fmaf(A.w,  xa.w, s);
    s = fmaf(Bv.x, xb.x, s); s = fmaf(Bv.y, xb.y, s);
    s = fmaf(Bv.z, xb.z, s); s = fmaf(Bv.w, xb.w, s);
    return s;
}

// GRU-Bayes event update, one sample, warp-collective
__device__ __forceinline__ void event_upd(
    float* __restrict__ hs, const float* __restrict__ xv,
    const float* __restrict__ sm,
    float ebr1, float ebr2, float ebz1, float ebz2,
    float ebi1, float ebi2, float ebh1, float ebh2,
    int lane, int o2)
{
    float4 xa = *(const float4*)xv, xb = *(const float4*)(xv + 4);
    float gir1 = dot8(sm + OF_WIH + lane*12,       xa, xb);
    float gir2 = dot8(sm + OF_WIH + (32+lane)*12,  xa, xb);
    float giz1 = dot8(sm + OF_WIH + (64+lane)*12,  xa, xb);
    float giz2 = dot8(sm + OF_WIH + (96+lane)*12,  xa, xb);
    float gin1 = dot8(sm + OF_WIH + (128+lane)*12, xa, xb);
    float gin2 = dot8(sm + OF_WIH + (160+lane)*12, xa, xb);
    const ul2* pE1 = (const ul2*)(sm + OF_WHH + lane*68);
    ull a1=0,a2=0,a3=0,a4=0,a5=0,a6=0;
    const ul2* hp = (const ul2*)hs;
    #pragma unroll
    for (int i = 0; i < 16; i++) {
        ul2 hv = hp[i];
        ul2 w1 = pE1[i],        w2 = pE1[i + 544];
        ul2 w3 = pE1[i + 1088], w4 = pE1[i + 1632];
        ul2 w5 = pE1[i + 2176], w6 = pE1[i + 2720];
        FMA2(a1, w1.x, hv.x, a1); FMA2(a1, w1.y, hv.y, a1);
        FMA2(a2, w2.x, hv.x, a2); FMA2(a2, w2.y, hv.y, a2);
        FMA2(a3, w3.x, hv.x, a3); FMA2(a3, w3.y, hv.y, a3);
        FMA2(a4, w4.x, hv.x, a4); FMA2(a4, w4.y, hv.y, a4);
        FMA2(a5, w5.x, hv.x, a5); FMA2(a5, w5.y, hv.y, a5);
        FMA2(a6, w6.x, hv.x, a6); FMA2(a6, w6.y, hv.y, a6);
    }
    float h1o = hs[lane], h2o = hs[o2];
    float r1 = sigm(gir1 + hadd2(a1) + ebr1);
    float r2 = sigm(gir2 + hadd2(a2) + ebr2);
    float z1 = sigm(giz1 + hadd2(a3) + ebz1);
    float z2 = sigm(giz2 + hadd2(a4) + ebz2);
    float n1 = tanh_f(gin1 + ebi1 + r1 * (hadd2(a5) + ebh1));
    float n2 = tanh_f(gin2 + ebi2 + r2 * (hadd2(a6) + ebh2));
    float h1n = fmaf(z1, h1o - n1, n1);      // (1-z)n + z h
    float h2n = fmaf(z2, h2o - n2, n2);
    __syncwarp();
    hs[lane] = h1n; hs[o2] = h2n;
    __syncwarp();
}

__global__ __launch_bounds__(128, 1)
void ev_gru_main(
    const float* __restrict__ X,
    const float* __restrict__ covs,
    const float* __restrict__ cW1, const float* __restrict__ cb1,
    const float* __restrict__ cW2, const float* __restrict__ cb2,
    const float* __restrict__ gWih, const float* __restrict__ gWhh,
    const float* __restrict__ gbih, const float* __restrict__ gbhh,
    const float* __restrict__ gxb,
    const float* __restrict__ ghrW, const float* __restrict__ ghzW,
    const float* __restrict__ ghhW)
{
    extern __shared__ float sm[];
    const int tid = threadIdx.x, blk = blockIdx.x;
    const int warp = tid >> 5, lane = tid & 31, o2 = lane + 32;
    int* swin = (int*)(sm + OF_WIN);

    // ---- staging (stride 128) ----
    for (int i = tid; i < 64*64; i += 128) {
        int r = i >> 6, c = i & 63;
        sm[OF_GHR + r*68 + c] = ghrW[i];
        sm[OF_GHZ + r*68 + c] = ghzW[i];
        sm[OF_GHH + r*68 + c] = ghhW[i];
    }
    for (int i = tid; i < 192*64; i += 128) {
        int r = i >> 6, c = i & 63;
        sm[OF_WHH + r*68 + c] = gWhh[i];
    }
    for (int i = tid; i < 192*8; i += 128) {
        int r = i >> 3, c = i & 7;
        sm[OF_WIH + r*12 + c] = gWih[i];
    }
    for (int i = tid; i < 192; i += 128) {
        sm[OF_BIH + i] = gbih[i];
        sm[OF_BHH + i] = gbhh[i];
        sm[OF_GXB + i] = gxb[i];
    }

    const int sA = warp*2, sB = sA + 1;
    const int bA = blk*8 + sA, bB = bA + 1;
    float* hA = sm + OF_HS + sA*64;  float* hB = sm + OF_HS + sB*64;
    float* rA = sm + OF_RS + sA*64;  float* rB = sm + OF_RS + sB*64;

    // ---- h0 init (warp-local, 2 samples) ----
    #pragma unroll
    for (int pick = 0; pick < 2; pick++) {
        const int b = pick ? bB : bA;
        float* hs = pick ? hB : hA;
        float* rs = pick ? rB : rA;
        float t1 = __ldg(cb1 + lane), t2 = __ldg(cb1 + o2);
        #pragma unroll
        for (int k = 0; k < 16; k++) {
            float cv = __ldg(covs + b*16 + k);
            t1 = fmaf(cv, __ldg(cW1 + lane*16 + k), t1);
            t2 = fmaf(cv, __ldg(cW1 + o2*16   + k), t2);
        }
        rs[lane] = fmaxf(t1, 0.f); rs[o2] = fmaxf(t2, 0.f);
        __syncwarp();
        float a1 = __ldg(cb2 + lane), a2 = __ldg(cb2 + o2);
        #pragma unroll 8
        for (int c = 0; c < 64; c++) {
            float tv = rs[c];
            a1 = fmaf(tv, __ldg(cW2 + lane*64 + c), a1);
            a2 = fmaf(tv, __ldg(cW2 + o2*64   + c), a2);
        }
        __syncwarp();
        hs[lane] = tanh_f(a1); hs[o2] = tanh_f(a2);
        __syncwarp();
    }
    // t=0 winner/X prefetch (warp-local: lanes 0-1 handle this warp's samples)
    if (lane < 2) {
        int w = __ldg(g_winner + bA + lane);
        swin[sA + lane] = w;
        if (w >= 0) {
            const float4* xp = (const float4*)(X + (size_t)w*8);
            float4 xa = __ldg(xp), xb = __ldg(xp + 1);
            float4* dst = (float4*)(sm + OF_XV + (sA + lane)*8);
            dst[0] = xa; dst[1] = xb;
        }
    }
    __syncthreads();   // weights staged (one-time)

    // ---- stationary pointers / scalars ----
    const ul2* pR1 = (const ul2*)(sm + OF_GHR + lane*68);
    const ul2* pR2 = (const ul2*)(sm + OF_GHR + (lane+32)*68);
    const ul2* pZ1 = (const ul2*)(sm + OF_GHZ + lane*68);
    const ul2* pZ2 = (const ul2*)(sm + OF_GHZ + (lane+32)*68);
    const ul2* pU1 = (const ul2*)(sm + OF_GHH + lane*68);
    const ul2* pU2 = (const ul2*)(sm + OF_GHH + (lane+32)*68);
    const ul2* hpA = (const ul2*)hA;  const ul2* hpB = (const ul2*)hB;
    const ul2* rpA = (const ul2*)rA;  const ul2* rpB = (const ul2*)rB;

    const float xr1 = sm[OF_GXB + lane],       xr2 = sm[OF_GXB + o2];
    const float xz1 = sm[OF_GXB + 64 + lane],  xz2 = sm[OF_GXB + 64 + o2];
    const float xh1 = sm[OF_GXB + 128 + lane], xh2 = sm[OF_GXB + 128 + o2];
    const float ebr1 = sm[OF_BIH + lane]      + sm[OF_BHH + lane];
    const float ebr2 = sm[OF_BIH + o2]        + sm[OF_BHH + o2];
    const float ebz1 = sm[OF_BIH + 64 + lane] + sm[OF_BHH + 64 + lane];
    const float ebz2 = sm[OF_BIH + 64 + o2]   + sm[OF_BHH + 64 + o2];
    const float ebi1 = sm[OF_BIH + 128 + lane], ebi2 = sm[OF_BIH + 128 + o2];
    const float ebh1 = sm[OF_BHH + 128 + lane], ebh2 = sm[OF_BHH + 128 + o2];

    // ================= main loop (warp-independent) =================
    for (int t = 0; ; t++) {
        const int pb = t & 1;

        // ---- events (last-dup wins; from pre-update h) ----
        if (t < NEV) {
            if (swin[pb*8 + sA] >= 0)
                event_upd(hA, sm + OF_XV + pb*64 + sA*8, sm,
                          ebr1,ebr2,ebz1,ebz2,ebi1,ebi2,ebh1,ebh2, lane, o2);
            if (swin[pb*8 + sB] >= 0)
                event_upd(hB, sm + OF_XV + pb*64 + sB*8, sm,
                          ebr1,ebr2,ebz1,ebz2,ebi1,ebi2,ebh1,ebh2, lane, o2);
        }

        // ---- h_rec store (post-event, pre-ODE) ----
        {
            float* base = g_hrec + ((size_t)t*B_ + bA)*64;
            float2 vA = *(const float2*)(hA + lane*2);
            float2 vB = *(const float2*)(hB + lane*2);
            *(float2*)(base + lane*2)      = vA;
            *(float2*)(base + 64 + lane*2) = vB;
        }
        if (t == NSTEPS) break;

        // warp-local prefetch of winners for t+1
        int pw = -1;
        const bool pf = (t + 1 < NEV) && (lane < 2);
        if (pf) pw = __ldg(g_winner + (t+1)*B_ + bA + lane);

        // ---- PASS1: gates r,z (4 weight rowsets x 2 samples) ----
        ull aR1A=0, aR1B=0, aR2A=0, aR2B=0, aZ1A=0, aZ1B=0, aZ2A=0, aZ2B=0;
        #pragma unroll
        for (int i = 0; i < 16; i++) {
            ul2 hvA = hpA[i], hvB = hpB[i];
            ul2 w;
            w = pR1[i];
            FMA2(aR1A, w.x, hvA.x, aR1A); FMA2(aR1A, w.y, hvA.y, aR1A);
            FMA2(aR1B, w.x, hvB.x, aR1B); FMA2(aR1B, w.y, hvB.y, aR1B);
            w = pR2[i];
            FMA2(aR2A, w.x, hvA.x, aR2A); FMA2(aR2A, w.y, hvA.y, aR2A);
            FMA2(aR2B, w.x, hvB.x, aR2B); FMA2(aR2B, w.y, hvB.y, aR2B);
            w = pZ1[i];
            FMA2(aZ1A, w.x, hvA.x, aZ1A); FMA2(aZ1A, w.y, hvA.y, aZ1A);
            FMA2(aZ1B, w.x, hvB.x, aZ1B); FMA2(aZ1B, w.y, hvB.y, aZ1B);
            w = pZ2[i];
            FMA2(aZ2A, w.x, hvA.x, aZ2A); FMA2(aZ2A, w.y, hvA.y, aZ2A);
            FMA2(aZ2B, w.x, hvB.x, aZ2B); FMA2(aZ2B, w.y, hvB.y, aZ2B);
        }
        float h1A = hA[lane], h2A = hA[o2];
        float h1B = hB[lane], h2B = hB[o2];
        float r1A = sigm(hadd2(aR1A) + xr1), r2A = sigm(hadd2(aR2A) + xr2);
        float r1B = sigm(hadd2(aR1B) + xr1), r2B = sigm(hadd2(aR2B) + xr2);
        float z1A = sigm(hadd2(aZ1A) + xz1), z2A = sigm(hadd2(aZ2A) + xz2);
        float z1B = sigm(hadd2(aZ1B) + xz1), z2B = sigm(hadd2(aZ2B) + xz2);
        __syncwarp();
        rA[lane] = r1A * h1A; rA[o2] = r2A * h2A;
        rB[lane] = r1B * h1B; rB[o2] = r2B * h2B;
        // prefetch stores (warp-local)
        if (pf) {
            swin[(pb ^ 1)*8 + sA + lane] = pw;
            if (pw >= 0) {
                const float4* xp = (const float4*)(X + (size_t)pw*8);
                float4 xa = __ldg(xp), xb = __ldg(xp + 1);
                float4* dst = (float4*)(sm + OF_XV + (pb^1)*64 + (sA+lane)*8);
                dst[0] = xa; dst[1] = xb;
            }
        }
        __syncwarp();

        // ---- PASS2: ghh on (r*h); Euler update ----
        ull u1A=0, u1B=0, u2A=0, u2B=0;
        #pragma unroll
        for (int i = 0; i < 16; i++) {
            ul2 rvA = rpA[i], rvB = rpB[i];
            ul2 w;
            w = pU1[i];
            FMA2(u1A, w.x, rvA.x, u1A); FMA2(u1A, w.y, rvA.y, u1A);
            FMA2(u1B, w.x, rvB.x, u1B); FMA2(u1B, w.y, rvB.y, u1B);
            w = pU2[i];
            FMA2(u2A, w.x, rvA.x, u2A); FMA2(u2A, w.y, rvA.y, u2A);
            FMA2(u2B, w.x, rvB.x, u2B); FMA2(u2B, w.y, rvB.y, u2B);
        }
        float uu1A = tanh_f(xh1 + hadd2(u1A)), uu2A = tanh_f(xh2 + hadd2(u2A));
        float uu1B = tanh_f(xh1 + hadd2(u1B)), uu2B = tanh_f(xh2 + hadd2(u2B));
        float h1An = fmaf(DT_*(1.f - z1A), uu1A - h1A, h1A);
        float h2An = fmaf(DT_*(1.f - z2A), uu2A - h2A, h2A);
        float h1Bn = fmaf(DT_*(1.f - z1B), uu1B - h1B, h1B);
        float h2Bn = fmaf(DT_*(1.f - z2B), uu2B - h2B, h2B);
        __syncwarp();
        hA[lane] = h1An; hA[o2] = h2An;
        hB[lane] = h1Bn; hB[o2] = h2Bn;
        __syncwarp();
    }
}

// ---------------- K2: batched output head (4 pairs/warp) ----------------
__global__ __launch_bounds__(256, 2)
void head_k(const float* __restrict__ oW1, const float* __restrict__ ob1,
            const float* __restrict__ oW2, const float* __restrict__ ob2,
            float* __restrict__ out)
{
    extern __shared__ float sm[];
    const int tid = threadIdx.x, warp = tid >> 5, lane = tid & 31;

    for (int i = tid; i < 128*64; i += 256) {
        int r = i >> 6, c = i & 63;
        sm[SH_W1 + r*68 + c] = oW1[i];
    }
    if (tid < 128) sm[SH_OB1 + tid] = ob1[tid];
    sm[SH_W2 + tid] = oW2[tid];
    if (tid < 2) sm[SH_OB2 + tid] = ob2[tid];

    // load 4 contiguous (t,b) pairs' h (256 floats) into this warp's slot
    const size_t base = ((size_t)blockIdx.x*8 + warp)*4;
    {
        const float4* hb = (const float4*)(g_hrec + base*64);
        float4* sh4 = (float4*)(sm + SH_H + warp*256);
        sh4[lane]      = __ldg(hb + lane);
        sh4[lane + 32] = __ldg(hb + lane + 32);
    }
    __syncthreads();

    const ul2* pA = (const ul2*)(sm + SH_W1 + lane*68);
    const ul2* pB = (const ul2*)(sm + SH_W1 + (lane+32)*68);
    const ul2* pC = (const ul2*)(sm + SH_W1 + (lane+64)*68);
    const ul2* pD = (const ul2*)(sm + SH_W1 + (lane+96)*68);
    const ul2* hw = (const ul2*)(sm + SH_H + warp*256);
    const float hb0 = sm[SH_OB1 + lane],      hb1 = sm[SH_OB1 + lane + 32];
    const float hb2 = sm[SH_OB1 + lane + 64], hb3 = sm[SH_OB1 + lane + 96];
    const float w200 = sm[SH_W2 + lane],      w201 = sm[SH_W2 + lane + 32];
    const float w202 = sm[SH_W2 + lane + 64], w203 = sm[SH_W2 + lane + 96];
    const float w210 = sm[SH_W2 + 128 + lane],      w211 = sm[SH_W2 + 128 + lane + 32];
    const float w212 = sm[SH_W2 + 128 + lane + 64], w213 = sm[SH_W2 + 128 + lane + 96];
    const float b20 = sm[SH_OB2], b21 = sm[SH_OB2 + 1];

    ull aA[4], aB[4], aC[4], aD[4];
    #pragma unroll
    for (int p = 0; p < 4; p++) { aA[p]=0; aB[p]=0; aC[p]=0; aD[p]=0; }
    #pragma unroll
    for (int i = 0; i < 16; i++) {
        ul2 wa = pA[i], wb = pB[i], wc = pC[i], wd = pD[i];
        #pragma unroll
        for (int p = 0; p < 4; p++) {
            ul2 hv = hw[p*16 + i];
            FMA2(aA[p], wa.x, hv.x, aA[p]); FMA2(aA[p], wa.y, hv.y, aA[p]);
            FMA2(aB[p], wb.x, hv.x, aB[p]); FMA2(aB[p], wb.y, hv.y, aB[p]);
            FMA2(aC[p], wc.x, hv.x, aC[p]); FMA2(aC[p], wc.y, hv.y, aC[p]);
            FMA2(aD[p], wd.x, hv.x, aD[p]); FMA2(aD[p], wd.y, hv.y, aD[p]);
        }
    }
    #pragma unroll
    for (int p = 0; p < 4; p++) {
        float d0 = fmaxf(hadd2(aA[p]) + hb0, 0.f);
        float d1 = fmaxf(hadd2(aB[p]) + hb1, 0.f);
        float d2 = fmaxf(hadd2(aC[p]) + hb2, 0.f);
        float d3 = fmaxf(hadd2(aD[p]) + hb3, 0.f);
        float p0 = d0*w200; p0 = fmaf(d1,w201,p0); p0 = fmaf(d2,w202,p0); p0 = fmaf(d3,w203,p0);
        float p1 = d0*w210; p1 = fmaf(d1,w211,p1); p1 = fmaf(d2,w212,p1); p1 = fmaf(d3,w213,p1);
        #pragma unroll
        for (int s = 16; s > 0; s >>= 1) {
            p0 += __shfl_xor_sync(0xffffffffu, p0, s);
            p1 += __shfl_xor_sync(0xffffffffu, p1, s);
        }
        if (lane == 0) {
            float2 v = {p0 + b20, p1 + b21};
            *(float2*)(out + (base + p)*2) = v;
        }
    }
}

extern "C" void kernel_launch(void* const* d_in, const int* in_sizes, int n_in,
                              void* d_out, int out_size)
{
    (void)in_sizes; (void)n_in; (void)out_size;
    const float* X    = (const float*)d_in[2];
    const int*   sid  = (const int*)  d_in[3];
    const float* covs = (const float*)d_in[4];
    const float* cW1  = (const float*)d_in[6];
    const float* cb1  = (const float*)d_in[7];
    const float* cW2  = (const float*)d_in[8];
    const float* cb2  = (const float*)d_in[9];
    const float* gWih = (const float*)d_in[10];
    const float* gWhh = (const float*)d_in[11];
    const float* gbih = (const float*)d_in[12];
    const float* gbhh = (const float*)d_in[13];
    const float* gxb  = (const float*)d_in[15];
    const float* ghrW = (const float*)d_in[16];
    const float* ghzW = (const float*)d_in[17];
    const float* ghhW = (const float*)d_in[18];
    const float* oW1  = (const float*)d_in[19];
    const float* ob1  = (const float*)d_in[20];
    const float* oW2  = (const float*)d_in[21];
    const float* ob2  = (const float*)d_in[22];
    float* out = (float*)d_out;

    winner_init_k<<<(NEV*B_ + 255)/256, 256>>>();
    winner_scatter_k<<<(TOT_ + 255)/256, 256>>>(sid);

    size_t sm_main = SM_MAIN * sizeof(float);
    cudaFuncSetAttribute(ev_gru_main, cudaFuncAttributeMaxDynamicSharedMemorySize, (int)sm_main);
    ev_gru_main<<<B_/8, 128, sm_main>>>(X, covs, cW1, cb1, cW2, cb2,
                                        gWih, gWhh, gbih, gbhh, gxb,
                                        ghrW, ghzW, ghhW);

    size_t sm_head = SM_HEAD * sizeof(float);
    cudaFuncSetAttribute(head_k, cudaFuncAttributeMaxDynamicSharedMemorySize, (int)sm_head);
    head_k<<<(NSTEPS + 1) * B_ / 32, 256, sm_head>>>(oW1, ob1, oW2, ob2, out);
}

// round 11
// speedup vs baseline: 1.4844x; 1.0488x over previous
#include <cuda_runtime.h>

// ---------------------------------------------------------------------------
// EventGRUBayes — two-kernel split.
// K1: warp-independent recurrence (128 blk x 128 thr, 4 warps x 2 samples),
//     no head; h_rec streamed to g_hrec.  [UNCHANGED from R9 — proven]
// K2: batched head v2 — 8 pairs/warp, 4 W1 rowsets concurrent, W2 folded
//     into rowset epilogue (no w2v array) -> <=128 regs, 2 blocks/SM,
//     48 crossbar wavefronts per (t,b) pair.
// ---------------------------------------------------------------------------

#define B_     1024
#define NEV    400
#define NSTEPS 500
#define TOT_   (NEV * 256)
#define DT_    0.01f

typedef unsigned long long ull;
typedef ulonglong2 ul2;

// K1 smem float offsets (rows padded 64->68 / 8->12)
#define OF_GHR 0
#define OF_GHZ 4352
#define OF_GHH 8704
#define OF_WHH 13056
#define OF_WIH 26112
#define OF_BIH 28416
#define OF_BHH 28608
#define OF_GXB 28800
#define OF_HS  28992
#define OF_RS  29504
#define OF_WIN 30016          // [2][8] ints
#define OF_XV  30032          // [2][8][8]
#define SM_MAIN 30160         // 120640 bytes

// K2 smem float offsets
#define SH_W1  0              // 128*68
#define SH_H   8704           // 8 warps * 512 (8 pairs x 64)
#define SH_OB1 12800
#define SH_W2  12928
#define SH_OB2 13184
#define SM_HEAD 13188         // 52752 bytes

__device__ int   g_winner[NEV * B_];
__device__ float g_hrec[(size_t)(NSTEPS + 1) * B_ * 64];   // [t][b][64]

__global__ void winner_init_k() {
    int i = blockIdx.x * blockDim.x + threadIdx.x;
    if (i < NEV * B_) g_winner[i] = -1;
}
__global__ void winner_scatter_k(const int* __restrict__ sid) {
    int j = blockIdx.x * blockDim.x + threadIdx.x;
    if (j < TOT_) atomicMax(&g_winner[(j >> 8) * B_ + sid[j]], j);
}

__device__ __forceinline__ float sigm(float x) {
    return __fdividef(1.f, 1.f + __expf(-x));
}
__device__ __forceinline__ float tanh_f(float x) {
    float xc = fminf(fmaxf(x, -15.f), 15.f);
    float e  = __expf(-2.f * xc);
    return __fdividef(1.f - e, 1.f + e);
}
#define FMA2(d, a, b, c) \
    asm("fma.rn.f32x2 %0, %1, %2, %3;" : "=l"(d) : "l"(a), "l"(b), "l"(c))
__device__ __forceinline__ float hadd2(ull v) {
    unsigned lo, hi;
    asm("mov.b64 {%0, %1}, %2;" : "=r"(lo), "=r"(hi) : "l"(v));
    return __uint_as_float(lo) + __uint_as_float(hi);
}
__device__ __forceinline__ float dot8(const float* __restrict__ w, float4 xa, float4 xb) {
    float4 A  = *reinterpret_cast<const float4*>(w);
    float4 Bv = *reinterpret_cast<const float4*>(w + 4);
    float s = A.x * xa.x;
    s = fmaf(A.y,  xa.y, s); s = fmaf(A.z,  xa.z, s); s = fmaf(A.w,  xa.w, s);
    s = fmaf(Bv.x, xb.x, s); s = fmaf(Bv.y, xb.y, s);
    s = fmaf(Bv.z, xb.z, s); s = fmaf(Bv.w, xb.w, s);
    return s;
}

// GRU-Bayes event update, one sample, warp-collective
__device__ __forceinline__ void event_upd(
    float* __restrict__ hs, const float* __restrict__ xv,
    const float* __restrict__ sm,
    float ebr1, float ebr2, float ebz1, float ebz2,
    float ebi1, float ebi2, float ebh1, float ebh2,
    int lane, int o2)
{
    float4 xa = *(const float4*)xv, xb = *(const float4*)(xv + 4);
    float gir1 = dot8(sm + OF_WIH + lane*12,       xa, xb);
    float gir2 = dot8(sm + OF_WIH + (32+lane)*12,  xa, xb);
    float giz1 = dot8(sm + OF_WIH + (64+lane)*12,  xa, xb);
    float giz2 = dot8(sm + OF_WIH + (96+lane)*12,  xa, xb);
    float gin1 = dot8(sm + OF_WIH + (128+lane)*12, xa, xb);
    float gin2 = dot8(sm + OF_WIH + (160+lane)*12, xa, xb);
    const ul2* pE1 = (const ul2*)(sm + OF_WHH + lane*68);
    ull a1=0,a2=0,a3=0,a4=0,a5=0,a6=0;
    const ul2* hp = (const ul2*)hs;
    #pragma unroll
    for (int i = 0; i < 16; i++) {
        ul2 hv = hp[i];
        ul2 w1 = pE1[i],        w2 = pE1[i + 544];
        ul2 w3 = pE1[i + 1088], w4 = pE1[i + 1632];
        ul2 w5 = pE1[i + 2176], w6 = pE1[i + 2720];
        FMA2(a1, w1.x, hv.x, a1); FMA2(a1, w1.y, hv.y, a1);
        FMA2(a2, w2.x, hv.x, a2); FMA2(a2, w2.y, hv.y, a2);
        FMA2(a3, w3.x, hv.x, a3); FMA2(a3, w3.y, hv.y, a3);
        FMA2(a4, w4.x, hv.x, a4); FMA2(a4, w4.y, hv.y, a4);
        FMA2(a5, w5.x, hv.x, a5); FMA2(a5, w5.y, hv.y, a5);
        FMA2(a6, w6.x, hv.x, a6); FMA2(a6, w6.y, hv.y, a6);
    }
    float h1o = hs[lane], h2o = hs[o2];
    float r1 = sigm(gir1 + hadd2(a1) + ebr1);
    float r2 = sigm(gir2 + hadd2(a2) + ebr2);
    float z1 = sigm(giz1 + hadd2(a3) + ebz1);
    float z2 = sigm(giz2 + hadd2(a4) + ebz2);
    float n1 = tanh_f(gin1 + ebi1 + r1 * (hadd2(a5) + ebh1));
    float n2 = tanh_f(gin2 + ebi2 + r2 * (hadd2(a6) + ebh2));
    float h1n = fmaf(z1, h1o - n1, n1);      // (1-z)n + z h
    float h2n = fmaf(z2, h2o - n2, n2);
    __syncwarp();
    hs[lane] = h1n; hs[o2] = h2n;
    __syncwarp();
}

__global__ __launch_bounds__(128, 1)
void ev_gru_main(
    const float* __restrict__ X,
    const float* __restrict__ covs,
    const float* __restrict__ cW1, const float* __restrict__ cb1,
    const float* __restrict__ cW2, const float* __restrict__ cb2,
    const float* __restrict__ gWih, const float* __restrict__ gWhh,
    const float* __restrict__ gbih, const float* __restrict__ gbhh,
    const float* __restrict__ gxb,
    const float* __restrict__ ghrW, const float* __restrict__ ghzW,
    const float* __restrict__ ghhW)
{
    extern __shared__ float sm[];
    const int tid = threadIdx.x, blk = blockIdx.x;
    const int warp = tid >> 5, lane = tid & 31, o2 = lane + 32;
    int* swin = (int*)(sm + OF_WIN);

    // ---- staging (stride 128) ----
    for (int i = tid; i < 64*64; i += 128) {
        int r = i >> 6, c = i & 63;
        sm[OF_GHR + r*68 + c] = ghrW[i];
        sm[OF_GHZ + r*68 + c] = ghzW[i];
        sm[OF_GHH + r*68 + c] = ghhW[i];
    }
    for (int i = tid; i < 192*64; i += 128) {
        int r = i >> 6, c = i & 63;
        sm[OF_WHH + r*68 + c] = gWhh[i];
    }
    for (int i = tid; i < 192*8; i += 128) {
        int r = i >> 3, c = i & 7;
        sm[OF_WIH + r*12 + c] = gWih[i];
    }
    for (int i = tid; i < 192; i += 128) {
        sm[OF_BIH + i] = gbih[i];
        sm[OF_BHH + i] = gbhh[i];
        sm[OF_GXB + i] = gxb[i];
    }

    const int sA = warp*2, sB = sA + 1;
    const int bA = blk*8 + sA, bB = bA + 1;
    float* hA = sm + OF_HS + sA*64;  float* hB = sm + OF_HS + sB*64;
    float* rA = sm + OF_RS + sA*64;  float* rB = sm + OF_RS + sB*64;

    // ---- h0 init (warp-local, 2 samples) ----
    #pragma unroll
    for (int pick = 0; pick < 2; pick++) {
        const int b = pick ? bB : bA;
        float* hs = pick ? hB : hA;
        float* rs = pick ? rB : rA;
        float t1 = __ldg(cb1 + lane), t2 = __ldg(cb1 + o2);
        #pragma unroll
        for (int k = 0; k < 16; k++) {
            float cv = __ldg(covs + b*16 + k);
            t1 = fmaf(cv, __ldg(cW1 + lane*16 + k), t1);
            t2 = fmaf(cv, __ldg(cW1 + o2*16   + k), t2);
        }
        rs[lane] = fmaxf(t1, 0.f); rs[o2] = fmaxf(t2, 0.f);
        __syncwarp();
        float a1 = __ldg(cb2 + lane), a2 = __ldg(cb2 + o2);
        #pragma unroll 8
        for (int c = 0; c < 64; c++) {
            float tv = rs[c];
            a1 = fmaf(tv, __ldg(cW2 + lane*64 + c), a1);
            a2 = fmaf(tv, __ldg(cW2 + o2*64   + c), a2);
        }
        __syncwarp();
        hs[lane] = tanh_f(a1); hs[o2] = tanh_f(a2);
        __syncwarp();
    }
    // t=0 winner/X prefetch (warp-local)
    if (lane < 2) {
        int w = __ldg(g_winner + bA + lane);
        swin[sA + lane] = w;
        if (w >= 0) {
            const float4* xp = (const float4*)(X + (size_t)w*8);
            float4 xa = __ldg(xp), xb = __ldg(xp + 1);
            float4* dst = (float4*)(sm + OF_XV + (sA + lane)*8);
            dst[0] = xa; dst[1] = xb;
        }
    }
    __syncthreads();   // weights staged (one-time)

    // ---- stationary pointers / scalars ----
    const ul2* pR1 = (const ul2*)(sm + OF_GHR + lane*68);
    const ul2* pR2 = (const ul2*)(sm + OF_GHR + (lane+32)*68);
    const ul2* pZ1 = (const ul2*)(sm + OF_GHZ + lane*68);
    const ul2* pZ2 = (const ul2*)(sm + OF_GHZ + (lane+32)*68);
    const ul2* pU1 = (const ul2*)(sm + OF_GHH + lane*68);
    const ul2* pU2 = (const ul2*)(sm + OF_GHH + (lane+32)*68);
    const ul2* hpA = (const ul2*)hA;  const ul2* hpB = (const ul2*)hB;
    const ul2* rpA = (const ul2*)rA;  const ul2* rpB = (const ul2*)rB;

    const float xr1 = sm[OF_GXB + lane],       xr2 = sm[OF_GXB + o2];
    const float xz1 = sm[OF_GXB + 64 + lane],  xz2 = sm[OF_GXB + 64 + o2];
    const float xh1 = sm[OF_GXB + 128 + lane], xh2 = sm[OF_GXB + 128 + o2];
    const float ebr1 = sm[OF_BIH + lane]      + sm[OF_BHH + lane];
    const float ebr2 = sm[OF_BIH + o2]        + sm[OF_BHH + o2];
    const float ebz1 = sm[OF_BIH + 64 + lane] + sm[OF_BHH + 64 + lane];
    const float ebz2 = sm[OF_BIH + 64 + o2]   + sm[OF_BHH + 64 + o2];
    const float ebi1 = sm[OF_BIH + 128 + lane], ebi2 = sm[OF_BIH + 128 + o2];
    const float ebh1 = sm[OF_BHH + 128 + lane], ebh2 = sm[OF_BHH + 128 + o2];

    // ================= main loop (warp-independent) =================
    for (int t = 0; ; t++) {
        const int pb = t & 1;

        // ---- events (last-dup wins; from pre-update h) ----
        if (t < NEV) {
            if (swin[pb*8 + sA] >= 0)
                event_upd(hA, sm + OF_XV + pb*64 + sA*8, sm,
                          ebr1,ebr2,ebz1,ebz2,ebi1,ebi2,ebh1,ebh2, lane, o2);
            if (swin[pb*8 + sB] >= 0)
                event_upd(hB, sm + OF_XV + pb*64 + sB*8, sm,
                          ebr1,ebr2,ebz1,ebz2,ebi1,ebi2,ebh1,ebh2, lane, o2);
        }

        // ---- h_rec store (post-event, pre-ODE) ----
        {
            float* base = g_hrec + ((size_t)t*B_ + bA)*64;
            float2 vA = *(const float2*)(hA + lane*2);
            float2 vB = *(const float2*)(hB + lane*2);
            *(float2*)(base + lane*2)      = vA;
            *(float2*)(base + 64 + lane*2) = vB;
        }
        if (t == NSTEPS) break;

        // warp-local prefetch of winners for t+1
        int pw = -1;
        const bool pf = (t + 1 < NEV) && (lane < 2);
        if (pf) pw = __ldg(g_winner + (t+1)*B_ + bA + lane);

        // ---- PASS1: gates r,z (4 weight rowsets x 2 samples) ----
        ull aR1A=0, aR1B=0, aR2A=0, aR2B=0, aZ1A=0, aZ1B=0, aZ2A=0, aZ2B=0;
        #pragma unroll
        for (int i = 0; i < 16; i++) {
            ul2 hvA = hpA[i], hvB = hpB[i];
            ul2 w;
            w = pR1[i];
            FMA2(aR1A, w.x, hvA.x, aR1A); FMA2(aR1A, w.y, hvA.y, aR1A);
            FMA2(aR1B, w.x, hvB.x, aR1B); FMA2(aR1B, w.y, hvB.y, aR1B);
            w = pR2[i];
            FMA2(aR2A, w.x, hvA.x, aR2A); FMA2(aR2A, w.y, hvA.y, aR2A);
            FMA2(aR2B, w.x, hvB.x, aR2B); FMA2(aR2B, w.y, hvB.y, aR2B);
            w = pZ1[i];
            FMA2(aZ1A, w.x, hvA.x, aZ1A); FMA2(aZ1A, w.y, hvA.y, aZ1A);
            FMA2(aZ1B, w.x, hvB.x, aZ1B); FMA2(aZ1B, w.y, hvB.y, aZ1B);
            w = pZ2[i];
            FMA2(aZ2A, w.x, hvA.x, aZ2A); FMA2(aZ2A, w.y, hvA.y, aZ2A);
            FMA2(aZ2B, w.x, hvB.x, aZ2B); FMA2(aZ2B, w.y, hvB.y, aZ2B);
        }
        float h1A = hA[lane], h2A = hA[o2];
        float h1B = hB[lane], h2B = hB[o2];
        float r1A = sigm(hadd2(aR1A) + xr1), r2A = sigm(hadd2(aR2A) + xr2);
        float r1B = sigm(hadd2(aR1B) + xr1), r2B = sigm(hadd2(aR2B) + xr2);
        float z1A = sigm(hadd2(aZ1A) + xz1), z2A = sigm(hadd2(aZ2A) + xz2);
        float z1B = sigm(hadd2(aZ1B) + xz1), z2B = sigm(hadd2(aZ2B) + xz2);
        __syncwarp();
        rA[lane] = r1A * h1A; rA[o2] = r2A * h2A;
        rB[lane] = r1B * h1B; rB[o2] = r2B * h2B;
        if (pf) {
            swin[(pb ^ 1)*8 + sA + lane] = pw;
            if (pw >= 0) {
                const float4* xp = (const float4*)(X + (size_t)pw*8);
                float4 xa = __ldg(xp), xb = __ldg(xp + 1);
                float4* dst = (float4*)(sm + OF_XV + (pb^1)*64 + (sA+lane)*8);
                dst[0] = xa; dst[1] = xb;
            }
        }
        __syncwarp();

        // ---- PASS2: ghh on (r*h); Euler update ----
        ull u1A=0, u1B=0, u2A=0, u2B=0;
        #pragma unroll
        for (int i = 0; i < 16; i++) {
            ul2 rvA = rpA[i], rvB = rpB[i];
            ul2 w;
            w = pU1[i];
            FMA2(u1A, w.x, rvA.x, u1A); FMA2(u1A, w.y, rvA.y, u1A);
            FMA2(u1B, w.x, rvB.x, u1B); FMA2(u1B, w.y, rvB.y, u1B);
            w = pU2[i];
            FMA2(u2A, w.x, rvA.x, u2A); FMA2(u2A, w.y, rvA.y, u2A);
            FMA2(u2B, w.x, rvB.x, u2B); FMA2(u2B, w.y, rvB.y, u2B);
        }
        float uu1A = tanh_f(xh1 + hadd2(u1A)), uu2A = tanh_f(xh2 + hadd2(u2A));
        float uu1B = tanh_f(xh1 + hadd2(u1B)), uu2B = tanh_f(xh2 + hadd2(u2B));
        float h1An = fmaf(DT_*(1.f - z1A), uu1A - h1A, h1A);
        float h2An = fmaf(DT_*(1.f - z2A), uu2A - h2A, h2A);
        float h1Bn = fmaf(DT_*(1.f - z1B), uu1B - h1B, h1B);
        float h2Bn = fmaf(DT_*(1.f - z2B), uu2B - h2B, h2B);
        __syncwarp();
        hA[lane] = h1An; hA[o2] = h2An;
        hB[lane] = h1Bn; hB[o2] = h2Bn;
        __syncwarp();
    }
}

// ---------------- K2: batched head v2 (8 pairs/warp, folded W2) ----------------
__global__ __launch_bounds__(256, 2)
void head_k(const float* __restrict__ oW1, const float* __restrict__ ob1,
            const float* __restrict__ oW2, const float* __restrict__ ob2,
            float* __restrict__ out)
{
    extern __shared__ float sm[];
    const int tid = threadIdx.x, warp = tid >> 5, lane = tid & 31;

    for (int i = tid; i < 128*64; i += 256) {
        int r = i >> 6, c = i & 63;
        sm[SH_W1 + r*68 + c] = oW1[i];
    }
    if (tid < 128) sm[SH_OB1 + tid] = ob1[tid];
    sm[SH_W2 + tid] = oW2[tid];
    if (tid < 2) sm[SH_OB2 + tid] = ob2[tid];

    // load 8 contiguous (t,b) pairs' h (512 floats) into this warp's slot
    const size_t base = ((size_t)blockIdx.x*8 + warp)*8;
    {
        const float4* hb = (const float4*)(g_hrec + base*64);
        float4* sh4 = (float4*)(sm + SH_H + warp*512);
        #pragma unroll
        for (int k = 0; k < 4; k++) sh4[k*32 + lane] = __ldg(hb + k*32 + lane);
    }
    __syncthreads();

    // lane owns rows lane, lane+32, lane+64, lane+96 of W1 (4 rowsets)
    const ul2* pA = (const ul2*)(sm + SH_W1 + lane*68);
    const ul2* pB = (const ul2*)(sm + SH_W1 + (lane+32)*68);
    const ul2* pC = (const ul2*)(sm + SH_W1 + (lane+64)*68);
    const ul2* pD = (const ul2*)(sm + SH_W1 + (lane+96)*68);
    const ul2* hw = (const ul2*)(sm + SH_H + warp*512);     // h[p][i] = hw[p*16+i]
    const float bo0 = sm[SH_OB1 + lane],      bo1 = sm[SH_OB1 + lane + 32];
    const float bo2 = sm[SH_OB1 + lane + 64], bo3 = sm[SH_OB1 + lane + 96];
    // W2 scalars for this lane's 4 rows x 2 outputs (folds stage 2)
    const float wa0 = sm[SH_W2 + lane],        wa1 = sm[SH_W2 + 128 + lane];
    const float wb0 = sm[SH_W2 + 32 + lane],   wb1 = sm[SH_W2 + 160 + lane];
    const float wc0 = sm[SH_W2 + 64 + lane],   wc1 = sm[SH_W2 + 192 + lane];
    const float wd0 = sm[SH_W2 + 96 + lane],   wd1 = sm[SH_W2 + 224 + lane];
    const float b20 = sm[SH_OB2], b21 = sm[SH_OB2 + 1];

    ull aA[8], aB[8], aC[8], aD[8];
    #pragma unroll
    for (int p = 0; p < 8; p++) { aA[p]=0; aB[p]=0; aC[p]=0; aD[p]=0; }
    #pragma unroll
    for (int i = 0; i < 16; i++) {
        ul2 wa = pA[i], wb = pB[i], wc = pC[i], wd = pD[i];
        #pragma unroll
        for (int p = 0; p < 8; p++) {
            ul2 hv = hw[p*16 + i];
            FMA2(aA[p], wa.x, hv.x, aA[p]); FMA2(aA[p], wa.y, hv.y, aA[p]);
            FMA2(aB[p], wb.x, hv.x, aB[p]); FMA2(aB[p], wb.y, hv.y, aB[p]);
            FMA2(aC[p], wc.x, hv.x, aC[p]); FMA2(aC[p], wc.y, hv.y, aC[p]);
            FMA2(aD[p], wd.x, hv.x, aD[p]); FMA2(aD[p], wd.y, hv.y, aD[p]);
        }
    }
    #pragma unroll
    for (int p = 0; p < 8; p++) {
        float d0 = fmaxf(hadd2(aA[p]) + bo0, 0.f);
        float d1 = fmaxf(hadd2(aB[p]) + bo1, 0.f);
        float d2 = fmaxf(hadd2(aC[p]) + bo2, 0.f);
        float d3 = fmaxf(hadd2(aD[p]) + bo3, 0.f);
        float p0 = d0*wa0; p0 = fmaf(d1,wb0,p0); p0 = fmaf(d2,wc0,p0); p0 = fmaf(d3,wd0,p0);
        float p1 = d0*wa1; p1 = fmaf(d1,wb1,p1); p1 = fmaf(d2,wc1,p1); p1 = fmaf(d3,wd1,p1);
        #pragma unroll
        for (int s = 16; s > 0; s >>= 1) {
            p0 += __shfl_xor_sync(0xffffffffu, p0, s);
            p1 += __shfl_xor_sync(0xffffffffu, p1, s);
        }
        if (lane == 0) {
            float2 v = {p0 + b20, p1 + b21};
            *(float2*)(out + (base + p)*2) = v;
        }
    }
}

extern "C" void kernel_launch(void* const* d_in, const int* in_sizes, int n_in,
                              void* d_out, int out_size)
{
    (void)in_sizes; (void)n_in; (void)out_size;
    const float* X    = (const float*)d_in[2];
    const int*   sid  = (const int*)  d_in[3];
    const float* covs = (const float*)d_in[4];
    const float* cW1  = (const float*)d_in[6];
    const float* cb1  = (const float*)d_in[7];
    const float* cW2  = (const float*)d_in[8];
    const float* cb2  = (const float*)d_in[9];
    const float* gWih = (const float*)d_in[10];
    const float* gWhh = (const float*)d_in[11];
    const float* gbih = (const float*)d_in[12];
    const float* gbhh = (const float*)d_in[13];
    const float* gxb  = (const float*)d_in[15];
    const float* ghrW = (const float*)d_in[16];
    const float* ghzW = (const float*)d_in[17];
    const float* ghhW = (const float*)d_in[18];
    const float* oW1  = (const float*)d_in[19];
    const float* ob1  = (const float*)d_in[20];
    const float* oW2  = (const float*)d_in[21];
    const float* ob2  = (const float*)d_in[22];
    float* out = (float*)d_out;

    winner_init_k<<<(NEV*B_ + 255)/256, 256>>>();
    winner_scatter_k<<<(TOT_ + 255)/256, 256>>>(sid);

    size_t sm_main = SM_MAIN * sizeof(float);
    cudaFuncSetAttribute(ev_gru_main, cudaFuncAttributeMaxDynamicSharedMemorySize, (int)sm_main);
    ev_gru_main<<<B_/8, 128, sm_main>>>(X, covs, cW1, cb1, cW2, cb2,
                                        gWih, gWhh, gbih, gbhh, gxb,
                                        ghrW, ghzW, ghhW);

    size_t sm_head = SM_HEAD * sizeof(float);
    cudaFuncSetAttribute(head_k, cudaFuncAttributeMaxDynamicSharedMemorySize, (int)sm_head);
    head_k<<<(NSTEPS + 1) * B_ / 64, 256, sm_head>>>(oW1, ob1, oW2, ob2, out);
}

// round 12
// speedup vs baseline: 1.5052x; 1.0140x over previous
#include <cuda_runtime.h>

// ---------------------------------------------------------------------------
// EventGRUBayes — two-kernel split.
// K1: warp-independent recurrence (128 blk x 128 thr, 4 warps x 2 samples),
//     no head; h_rec streamed to g_hrec.  [UNCHANGED — proven]
// K2: batched head v3 — persistent-ish: 1336 blocks, each warp loops 6
//     batches of 8 pairs; W1 staged once per block; h double-buffered via
//     cp.async; no block syncs in the loop.
// ---------------------------------------------------------------------------

#define B_     1024
#define NEV    400
#define NSTEPS 500
#define TOT_   (NEV * 256)
#define DT_    0.01f

typedef unsigned long long ull;
typedef ulonglong2 ul2;

// K1 smem float offsets (rows padded 64->68 / 8->12)
#define OF_GHR 0
#define OF_GHZ 4352
#define OF_GHH 8704
#define OF_WHH 13056
#define OF_WIH 26112
#define OF_BIH 28416
#define OF_BHH 28608
#define OF_GXB 28800
#define OF_HS  28992
#define OF_RS  29504
#define OF_WIN 30016          // [2][8] ints
#define OF_XV  30032          // [2][8][8]
#define SM_MAIN 30160         // 120640 bytes

// K2 smem float offsets
#define SH_W1  0              // 128*68
#define SH_HB  8704           // 8 warps * 2 buffers * 512
#define SH_OB1 16896
#define SH_W2  17024
#define SH_OB2 17280
#define SM_HEAD 17282         // 69128 bytes

#define HEAD_L      6                       // batches per warp
#define HEAD_BLOCKS 1336                    // 1336*8*48 = 513024 pairs

__device__ int   g_winner[NEV * B_];
__device__ float g_hrec[(size_t)(NSTEPS + 1) * B_ * 64];   // [t][b][64]

__global__ void winner_init_k() {
    int i = blockIdx.x * blockDim.x + threadIdx.x;
    if (i < NEV * B_) g_winner[i] = -1;
}
__global__ void winner_scatter_k(const int* __restrict__ sid) {
    int j = blockIdx.x * blockDim.x + threadIdx.x;
    if (j < TOT_) atomicMax(&g_winner[(j >> 8) * B_ + sid[j]], j);
}

__device__ __forceinline__ float sigm(float x) {
    return __fdividef(1.f, 1.f + __expf(-x));
}
__device__ __forceinline__ float tanh_f(float x) {
    float xc = fminf(fmaxf(x, -15.f), 15.f);
    float e  = __expf(-2.f * xc);
    return __fdividef(1.f - e, 1.f + e);
}
#define FMA2(d, a, b, c) \
    asm("fma.rn.f32x2 %0, %1, %2, %3;" : "=l"(d) : "l"(a), "l"(b), "l"(c))
__device__ __forceinline__ float hadd2(ull v) {
    unsigned lo, hi;
    asm("mov.b64 {%0, %1}, %2;" : "=r"(lo), "=r"(hi) : "l"(v));
    return __uint_as_float(lo) + __uint_as_float(hi);
}
__device__ __forceinline__ float dot8(const float* __restrict__ w, float4 xa, float4 xb) {
    float4 A  = *reinterpret_cast<const float4*>(w);
    float4 Bv = *reinterpret_cast<const float4*>(w + 4);
    float s = A.x * xa.x;
    s = fmaf(A.y,  xa.y, s); s = fmaf(A.z,  xa.z, s); s = fmaf(A.w,  xa.w, s);
    s = fmaf(Bv.x, xb.x, s); s = fmaf(Bv.y, xb.y, s);
    s = fmaf(Bv.z, xb.z, s); s = fmaf(Bv.w, xb.w, s);
    return s;
}
#define CP_ASYNC16(saddr, gptr) \
    asm volatile("cp.async.cg.shared.global [%0], [%1], 16;" \
                 :: "r"(saddr), "l"(gptr) : "memory")
#define CP_COMMIT()  asm volatile("cp.async.commit_group;" ::: "memory")
#define CP_WAIT0()   asm volatile("cp.async.wait_group 0;" ::: "memory")

// GRU-Bayes event update, one sample, warp-collective
__device__ __forceinline__ void event_upd(
    float* __restrict__ hs, const float* __restrict__ xv,
    const float* __restrict__ sm,
    float ebr1, float ebr2, float ebz1, float ebz2,
    float ebi1, float ebi2, float ebh1, float ebh2,
    int lane, int o2)
{
    float4 xa = *(const float4*)xv, xb = *(const float4*)(xv + 4);
    float gir1 = dot8(sm + OF_WIH + lane*12,       xa, xb);
    float gir2 = dot8(sm + OF_WIH + (32+lane)*12,  xa, xb);
    float giz1 = dot8(sm + OF_WIH + (64+lane)*12,  xa, xb);
    float giz2 = dot8(sm + OF_WIH + (96+lane)*12,  xa, xb);
    float gin1 = dot8(sm + OF_WIH + (128+lane)*12, xa, xb);
    float gin2 = dot8(sm + OF_WIH + (160+lane)*12, xa, xb);
    const ul2* pE1 = (const ul2*)(sm + OF_WHH + lane*68);
    ull a1=0,a2=0,a3=0,a4=0,a5=0,a6=0;
    const ul2* hp = (const ul2*)hs;
    #pragma unroll
    for (int i = 0; i < 16; i++) {
        ul2 hv = hp[i];
        ul2 w1 = pE1[i],        w2 = pE1[i + 544];
        ul2 w3 = pE1[i + 1088], w4 = pE1[i + 1632];
        ul2 w5 = pE1[i + 2176], w6 = pE1[i + 2720];
        FMA2(a1, w1.x, hv.x, a1); FMA2(a1, w1.y, hv.y, a1);
        FMA2(a2, w2.x, hv.x, a2); FMA2(a2, w2.y, hv.y, a2);
        FMA2(a3, w3.x, hv.x, a3); FMA2(a3, w3.y, hv.y, a3);
        FMA2(a4, w4.x, hv.x, a4); FMA2(a4, w4.y, hv.y, a4);
        FMA2(a5, w5.x, hv.x, a5); FMA2(a5, w5.y, hv.y, a5);
        FMA2(a6, w6.x, hv.x, a6); FMA2(a6, w6.y, hv.y, a6);
    }
    float h1o = hs[lane], h2o = hs[o2];
    float r1 = sigm(gir1 + hadd2(a1) + ebr1);
    float r2 = sigm(gir2 + hadd2(a2) + ebr2);
    float z1 = sigm(giz1 + hadd2(a3) + ebz1);
    float z2 = sigm(giz2 + hadd2(a4) + ebz2);
    float n1 = tanh_f(gin1 + ebi1 + r1 * (hadd2(a5) + ebh1));
    float n2 = tanh_f(gin2 + ebi2 + r2 * (hadd2(a6) + ebh2));
    float h1n = fmaf(z1, h1o - n1, n1);      // (1-z)n + z h
    float h2n = fmaf(z2, h2o - n2, n2);
    __syncwarp();
    hs[lane] = h1n; hs[o2] = h2n;
    __syncwarp();
}

__global__ __launch_bounds__(128, 1)
void ev_gru_main(
    const float* __restrict__ X,
    const float* __restrict__ covs,
    const float* __restrict__ cW1, const float* __restrict__ cb1,
    const float* __restrict__ cW2, const float* __restrict__ cb2,
    const float* __restrict__ gWih, const float* __restrict__ gWhh,
    const float* __restrict__ gbih, const float* __restrict__ gbhh,
    const float* __restrict__ gxb,
    const float* __restrict__ ghrW, const float* __restrict__ ghzW,
    const float* __restrict__ ghhW)
{
    extern __shared__ float sm[];
    const int tid = threadIdx.x, blk = blockIdx.x;
    const int warp = tid >> 5, lane = tid & 31, o2 = lane + 32;
    int* swin = (int*)(sm + OF_WIN);

    // ---- staging (stride 128) ----
    for (int i = tid; i < 64*64; i += 128) {
        int r = i >> 6, c = i & 63;
        sm[OF_GHR + r*68 + c] = ghrW[i];
        sm[OF_GHZ + r*68 + c] = ghzW[i];
        sm[OF_GHH + r*68 + c] = ghhW[i];
    }
    for (int i = tid; i < 192*64; i += 128) {
        int r = i >> 6, c = i & 63;
        sm[OF_WHH + r*68 + c] = gWhh[i];
    }
    for (int i = tid; i < 192*8; i += 128) {
        int r = i >> 3, c = i & 7;
        sm[OF_WIH + r*12 + c] = gWih[i];
    }
    for (int i = tid; i < 192; i += 128) {
        sm[OF_BIH + i] = gbih[i];
        sm[OF_BHH + i] = gbhh[i];
        sm[OF_GXB + i] = gxb[i];
    }

    const int sA = warp*2, sB = sA + 1;
    const int bA = blk*8 + sA, bB = bA + 1;
    float* hA = sm + OF_HS + sA*64;  float* hB = sm + OF_HS + sB*64;
    float* rA = sm + OF_RS + sA*64;  float* rB = sm + OF_RS + sB*64;

    // ---- h0 init (warp-local, 2 samples) ----
    #pragma unroll
    for (int pick = 0; pick < 2; pick++) {
        const int b = pick ? bB : bA;
        float* hs = pick ? hB : hA;
        float* rs = pick ? rB : rA;
        float t1 = __ldg(cb1 + lane), t2 = __ldg(cb1 + o2);
        #pragma unroll
        for (int k = 0; k < 16; k++) {
            float cv = __ldg(covs + b*16 + k);
            t1 = fmaf(cv, __ldg(cW1 + lane*16 + k), t1);
            t2 = fmaf(cv, __ldg(cW1 + o2*16   + k), t2);
        }
        rs[lane] = fmaxf(t1, 0.f); rs[o2] = fmaxf(t2, 0.f);
        __syncwarp();
        float a1 = __ldg(cb2 + lane), a2 = __ldg(cb2 + o2);
        #pragma unroll 8
        for (int c = 0; c < 64; c++) {
            float tv = rs[c];
            a1 = fmaf(tv, __ldg(cW2 + lane*64 + c), a1);
            a2 = fmaf(tv, __ldg(cW2 + o2*64   + c), a2);
        }
        __syncwarp();
        hs[lane] = tanh_f(a1); hs[o2] = tanh_f(a2);
        __syncwarp();
    }
    // t=0 winner/X prefetch (warp-local)
    if (lane < 2) {
        int w = __ldg(g_winner + bA + lane);
        swin[sA + lane] = w;
        if (w >= 0) {
            const float4* xp = (const float4*)(X + (size_t)w*8);
            float4 xa = __ldg(xp), xb = __ldg(xp + 1);
            float4* dst = (float4*)(sm + OF_XV + (sA + lane)*8);
            dst[0] = xa; dst[1] = xb;
        }
    }
    __syncthreads();   // weights staged (one-time)

    // ---- stationary pointers / scalars ----
    const ul2* pR1 = (const ul2*)(sm + OF_GHR + lane*68);
    const ul2* pR2 = (const ul2*)(sm + OF_GHR + (lane+32)*68);
    const ul2* pZ1 = (const ul2*)(sm + OF_GHZ + lane*68);
    const ul2* pZ2 = (const ul2*)(sm + OF_GHZ + (lane+32)*68);
    const ul2* pU1 = (const ul2*)(sm + OF_GHH + lane*68);
    const ul2* pU2 = (const ul2*)(sm + OF_GHH + (lane+32)*68);
    const ul2* hpA = (const ul2*)hA;  const ul2* hpB = (const ul2*)hB;
    const ul2* rpA = (const ul2*)rA;  const ul2* rpB = (const ul2*)rB;

    const float xr1 = sm[OF_GXB + lane],       xr2 = sm[OF_GXB + o2];
    const float xz1 = sm[OF_GXB + 64 + lane],  xz2 = sm[OF_GXB + 64 + o2];
    const float xh1 = sm[OF_GXB + 128 + lane], xh2 = sm[OF_GXB + 128 + o2];
    const float ebr1 = sm[OF_BIH + lane]      + sm[OF_BHH + lane];
    const float ebr2 = sm[OF_BIH + o2]        + sm[OF_BHH + o2];
    const float ebz1 = sm[OF_BIH + 64 + lane] + sm[OF_BHH + 64 + lane];
    const float ebz2 = sm[OF_BIH + 64 + o2]   + sm[OF_BHH + 64 + o2];
    const float ebi1 = sm[OF_BIH + 128 + lane], ebi2 = sm[OF_BIH + 128 + o2];
    const float ebh1 = sm[OF_BHH + 128 + lane], ebh2 = sm[OF_BHH + 128 + o2];

    // ================= main loop (warp-independent) =================
    for (int t = 0; ; t++) {
        const int pb = t & 1;

        // ---- events (last-dup wins; from pre-update h) ----
        if (t < NEV) {
            if (swin[pb*8 + sA] >= 0)
                event_upd(hA, sm + OF_XV + pb*64 + sA*8, sm,
                          ebr1,ebr2,ebz1,ebz2,ebi1,ebi2,ebh1,ebh2, lane, o2);
            if (swin[pb*8 + sB] >= 0)
                event_upd(hB, sm + OF_XV + pb*64 + sB*8, sm,
                          ebr1,ebr2,ebz1,ebz2,ebi1,ebi2,ebh1,ebh2, lane, o2);
        }

        // ---- h_rec store (post-event, pre-ODE) ----
        {
            float* base = g_hrec + ((size_t)t*B_ + bA)*64;
            float2 vA = *(const float2*)(hA + lane*2);
            float2 vB = *(const float2*)(hB + lane*2);
            *(float2*)(base + lane*2)      = vA;
            *(float2*)(base + 64 + lane*2) = vB;
        }
        if (t == NSTEPS) break;

        // warp-local prefetch of winners for t+1
        int pw = -1;
        const bool pf = (t + 1 < NEV) && (lane < 2);
        if (pf) pw = __ldg(g_winner + (t+1)*B_ + bA + lane);

        // ---- PASS1: gates r,z (4 weight rowsets x 2 samples) ----
        ull aR1A=0, aR1B=0, aR2A=0, aR2B=0, aZ1A=0, aZ1B=0, aZ2A=0, aZ2B=0;
        #pragma unroll
        for (int i = 0; i < 16; i++) {
            ul2 hvA = hpA[i], hvB = hpB[i];
            ul2 w;
            w = pR1[i];
            FMA2(aR1A, w.x, hvA.x, aR1A); FMA2(aR1A, w.y, hvA.y, aR1A);
            FMA2(aR1B, w.x, hvB.x, aR1B); FMA2(aR1B, w.y, hvB.y, aR1B);
            w = pR2[i];
            FMA2(aR2A, w.x, hvA.x, aR2A); FMA2(aR2A, w.y, hvA.y, aR2A);
            FMA2(aR2B, w.x, hvB.x, aR2B); FMA2(aR2B, w.y, hvB.y, aR2B);
            w = pZ1[i];
            FMA2(aZ1A, w.x, hvA.x, aZ1A); FMA2(aZ1A, w.y, hvA.y, aZ1A);
            FMA2(aZ1B, w.x, hvB.x, aZ1B); FMA2(aZ1B, w.y, hvB.y, aZ1B);
            w = pZ2[i];
            FMA2(aZ2A, w.x, hvA.x, aZ2A); FMA2(aZ2A, w.y, hvA.y, aZ2A);
            FMA2(aZ2B, w.x, hvB.x, aZ2B); FMA2(aZ2B, w.y, hvB.y, aZ2B);
        }
        float h1A = hA[lane], h2A = hA[o2];
        float h1B = hB[lane], h2B = hB[o2];
        float r1A = sigm(hadd2(aR1A) + xr1), r2A = sigm(hadd2(aR2A) + xr2);
        float r1B = sigm(hadd2(aR1B) + xr1), r2B = sigm(hadd2(aR2B) + xr2);
        float z1A = sigm(hadd2(aZ1A) + xz1), z2A = sigm(hadd2(aZ2A) + xz2);
        float z1B = sigm(hadd2(aZ1B) + xz1), z2B = sigm(hadd2(aZ2B) + xz2);
        __syncwarp();
        rA[lane] = r1A * h1A; rA[o2] = r2A * h2A;
        rB[lane] = r1B * h1B; rB[o2] = r2B * h2B;
        if (pf) {
            swin[(pb ^ 1)*8 + sA + lane] = pw;
            if (pw >= 0) {
                const float4* xp = (const float4*)(X + (size_t)pw*8);
                float4 xa = __ldg(xp), xb = __ldg(xp + 1);
                float4* dst = (float4*)(sm + OF_XV + (pb^1)*64 + (sA+lane)*8);
                dst[0] = xa; dst[1] = xb;
            }
        }
        __syncwarp();

        // ---- PASS2: ghh on (r*h); Euler update ----
        ull u1A=0, u1B=0, u2A=0, u2B=0;
        #pragma unroll
        for (int i = 0; i < 16; i++) {
            ul2 rvA = rpA[i], rvB = rpB[i];
            ul2 w;
            w = pU1[i];
            FMA2(u1A, w.x, rvA.x, u1A); FMA2(u1A, w.y, rvA.y, u1A);
            FMA2(u1B, w.x, rvB.x, u1B); FMA2(u1B, w.y, rvB.y, u1B);
            w = pU2[i];
            FMA2(u2A, w.x, rvA.x, u2A); FMA2(u2A, w.y, rvA.y, u2A);
            FMA2(u2B, w.x, rvB.x, u2B); FMA2(u2B, w.y, rvB.y, u2B);
        }
        float uu1A = tanh_f(xh1 + hadd2(u1A)), uu2A = tanh_f(xh2 + hadd2(u2A));
        float uu1B = tanh_f(xh1 + hadd2(u1B)), uu2B = tanh_f(xh2 + hadd2(u2B));
        float h1An = fmaf(DT_*(1.f - z1A), uu1A - h1A, h1A);
        float h2An = fmaf(DT_*(1.f - z2A), uu2A - h2A, h2A);
        float h1Bn = fmaf(DT_*(1.f - z1B), uu1B - h1B, h1B);
        float h2Bn = fmaf(DT_*(1.f - z2B), uu2B - h2B, h2B);
        __syncwarp();
        hA[lane] = h1An; hA[o2] = h2An;
        hB[lane] = h1Bn; hB[o2] = h2Bn;
        __syncwarp();
    }
}

// ---------------- K2: batched head v3 (looped batches + cp.async) ----------
__global__ __launch_bounds__(256, 2)
void head_k(const float* __restrict__ oW1, const float* __restrict__ ob1,
            const float* __restrict__ oW2, const float* __restrict__ ob2,
            float* __restrict__ out)
{
    extern __shared__ float sm[];
    const int tid = threadIdx.x, warp = tid >> 5, lane = tid & 31;

    for (int i = tid; i < 128*64; i += 256) {
        int r = i >> 6, c = i & 63;
        sm[SH_W1 + r*68 + c] = oW1[i];
    }
    if (tid < 128) sm[SH_OB1 + tid] = ob1[tid];
    sm[SH_W2 + tid] = oW2[tid];
    if (tid < 2) sm[SH_OB2 + tid] = ob2[tid];

    const size_t warpbase = ((size_t)blockIdx.x*8 + warp) * (8*HEAD_L);
    // per-warp double buffer smem addresses (u32 for cp.async)
    const unsigned sbuf0 = (unsigned)__cvta_generic_to_shared(sm + SH_HB + warp*1024);
    const unsigned sbuf1 = sbuf0 + 512*4;

    // prefetch batch 0 into buffer 0 (4 x 16B per lane)
    {
        const float* g = g_hrec + warpbase*64;
        #pragma unroll
        for (int k = 0; k < 4; k++)
            CP_ASYNC16(sbuf0 + (lane + k*32)*16, g + (lane + k*32)*4);
        CP_COMMIT();
    }
    __syncthreads();   // W1/biases staged
    CP_WAIT0();
    __syncwarp();

    // lane owns W1 rows lane, lane+32, lane+64, lane+96
    const ul2* pA = (const ul2*)(sm + SH_W1 + lane*68);
    const ul2* pB = (const ul2*)(sm + SH_W1 + (lane+32)*68);
    const ul2* pC = (const ul2*)(sm + SH_W1 + (lane+64)*68);
    const ul2* pD = (const ul2*)(sm + SH_W1 + (lane+96)*68);
    const float bo0 = sm[SH_OB1 + lane],      bo1 = sm[SH_OB1 + lane + 32];
    const float bo2 = sm[SH_OB1 + lane + 64], bo3 = sm[SH_OB1 + lane + 96];
    const float wa0 = sm[SH_W2 + lane],        wa1 = sm[SH_W2 + 128 + lane];
    const float wb0 = sm[SH_W2 + 32 + lane],   wb1 = sm[SH_W2 + 160 + lane];
    const float wc0 = sm[SH_W2 + 64 + lane],   wc1 = sm[SH_W2 + 192 + lane];
    const float wd0 = sm[SH_W2 + 96 + lane],   wd1 = sm[SH_W2 + 224 + lane];
    const float b20 = sm[SH_OB2], b21 = sm[SH_OB2 + 1];

    for (int l = 0; l < HEAD_L; l++) {
        const int pb = l & 1;
        // prefetch next batch into alternate buffer
        if (l + 1 < HEAD_L) {
            const float* g = g_hrec + (warpbase + (size_t)(l+1)*8)*64;
            const unsigned dst = pb ? sbuf0 : sbuf1;
            #pragma unroll
            for (int k = 0; k < 4; k++)
                CP_ASYNC16(dst + (lane + k*32)*16, g + (lane + k*32)*4);
            CP_COMMIT();
        }
        const ul2* hw = (const ul2*)(sm + SH_HB + warp*1024 + pb*512);

        ull aA[8], aB[8], aC[8], aD[8];
        #pragma unroll
        for (int p = 0; p < 8; p++) { aA[p]=0; aB[p]=0; aC[p]=0; aD[p]=0; }
        #pragma unroll
        for (int i = 0; i < 16; i++) {
            ul2 wa = pA[i], wb = pB[i], wc = pC[i], wd = pD[i];
            #pragma unroll
            for (int p = 0; p < 8; p++) {
                ul2 hv = hw[p*16 + i];
                FMA2(aA[p], wa.x, hv.x, aA[p]); FMA2(aA[p], wa.y, hv.y, aA[p]);
                FMA2(aB[p], wb.x, hv.x, aB[p]); FMA2(aB[p], wb.y, hv.y, aB[p]);
                FMA2(aC[p], wc.x, hv.x, aC[p]); FMA2(aC[p], wc.y, hv.y, aC[p]);
                FMA2(aD[p], wd.x, hv.x, aD[p]); FMA2(aD[p], wd.y, hv.y, aD[p]);
            }
        }
        const size_t base = warpbase + (size_t)l*8;
        #pragma unroll
        for (int p = 0; p < 8; p++) {
            float d0 = fmaxf(hadd2(aA[p]) + bo0, 0.f);
            float d1 = fmaxf(hadd2(aB[p]) + bo1, 0.f);
            float d2 = fmaxf(hadd2(aC[p]) + bo2, 0.f);
            float d3 = fmaxf(hadd2(aD[p]) + bo3, 0.f);
            float p0 = d0*wa0; p0 = fmaf(d1,wb0,p0); p0 = fmaf(d2,wc0,p0); p0 = fmaf(d3,wd0,p0);
            float p1 = d0*wa1; p1 = fmaf(d1,wb1,p1); p1 = fmaf(d2,wc1,p1); p1 = fmaf(d3,wd1,p1);
            #pragma unroll
            for (int s = 16; s > 0; s >>= 1) {
                p0 += __shfl_xor_sync(0xffffffffu, p0, s);
                p1 += __shfl_xor_sync(0xffffffffu, p1, s);
            }
            if (lane == 0) {
                float2 v = {p0 + b20, p1 + b21};
                *(float2*)(out + (base + p)*2) = v;
            }
        }
        if (l + 1 < HEAD_L) {
            CP_WAIT0();
            __syncwarp();
        }
    }
}

extern "C" void kernel_launch(void* const* d_in, const int* in_sizes, int n_in,
                              void* d_out, int out_size)
{
    (void)in_sizes; (void)n_in; (void)out_size;
    const float* X    = (const float*)d_in[2];
    const int*   sid  = (const int*)  d_in[3];
    const float* covs = (const float*)d_in[4];
    const float* cW1  = (const float*)d_in[6];
    const float* cb1  = (const float*)d_in[7];
    const float* cW2  = (const float*)d_in[8];
    const float* cb2  = (const float*)d_in[9];
    const float* gWih = (const float*)d_in[10];
    const float* gWhh = (const float*)d_in[11];
    const float* gbih = (const float*)d_in[12];
    const float* gbhh = (const float*)d_in[13];
    const float* gxb  = (const float*)d_in[15];
    const float* ghrW = (const float*)d_in[16];
    const float* ghzW = (const float*)d_in[17];
    const float* ghhW = (const float*)d_in[18];
    const float* oW1  = (const float*)d_in[19];
    const float* ob1  = (const float*)d_in[20];
    const float* oW2  = (const float*)d_in[21];
    const float* ob2  = (const float*)d_in[22];
    float* out = (float*)d_out;

    winner_init_k<<<(NEV*B_ + 255)/256, 256>>>();
    winner_scatter_k<<<(TOT_ + 255)/256, 256>>>(sid);

    size_t sm_main = SM_MAIN * sizeof(float);
    cudaFuncSetAttribute(ev_gru_main, cudaFuncAttributeMaxDynamicSharedMemorySize, (int)sm_main);
    ev_gru_main<<<B_/8, 128, sm_main>>>(X, covs, cW1, cb1, cW2, cb2,
                                        gWih, gWhh, gbih, gbhh, gxb,
                                        ghrW, ghzW, ghhW);

    size_t sm_head = SM_HEAD * sizeof(float);
    cudaFuncSetAttribute(head_k, cudaFuncAttributeMaxDynamicSharedMemorySize, (int)sm_head);
    head_k<<<HEAD_BLOCKS, 256, sm_head>>>(oW1, ob1, oW2, ob2, out);
}